// round 4
// baseline (speedup 1.0000x reference)
#include <cuda_runtime.h>
#include <cuda_bf16.h>
#include <math.h>

#define B_ 4
#define S_ 2048
#define DIN 2048
#define DOUT 2048
#define DEPTH 11
#define NLEV (DEPTH + 1)          // 12
#define NNODES 4095
#define NTOK (B_ * S_)            // 8192
#define NLEAF 2048
#define LEAF0 2047

#define TRN_BX 128                // ceil(4095/32)
#define TRN_BY 64                 // 2048/32
#define TRN_BLOCKS (TRN_BX * TRN_BY)   // 8192 (== NTOK, convenient interleave)

// Static scratch
__device__ float          g_wout_t[(size_t)NNODES * DOUT];
__device__ float          g_gel[NTOK * NLEV];
__device__ unsigned short g_nodes[NTOK * NLEV];
__device__ int            g_hist[NLEAF];
__device__ int            g_perm[NTOK];

__device__ __forceinline__ float gelu_exact(float s) {
    return 0.5f * s * (1.0f + erff(s * 0.70710678118654752440f));
}

__device__ __forceinline__ float dot8(const float4* xr, const float4* w) {
    float p0 = 0.f, p1 = 0.f;
#pragma unroll
    for (int j = 0; j < 8; j += 2) {
        p0 += xr[j].x * w[j].x + xr[j].y * w[j].y + xr[j].z * w[j].z + xr[j].w * w[j].w;
        p1 += xr[j+1].x * w[j+1].x + xr[j+1].y * w[j+1].y + xr[j+1].z * w[j+1].z + xr[j+1].w * w[j+1].w;
    }
    return p0 + p1;
}

// ---------------------------------------------------------------------------
// Fused: even blocks traverse (1 token per 64-thread CTA, 2 warps x 1024 dims,
// speculative both-children prefetch), odd blocks transpose w_out.
// ---------------------------------------------------------------------------
__global__ __launch_bounds__(64, 7) void fused_traverse_kernel(
    const float* __restrict__ x,
    const float* __restrict__ w_in,
    const float* __restrict__ w_out)
{
    __shared__ float tile[32][33];
    __shared__ float hx[2][2];            // [level parity][half]

    if (blockIdx.x & 1) {
        // -------- transpose partition (w_out [DOUT,NNODES] -> g_wout_t) ----
        const int tb  = blockIdx.x >> 1;
        const int nx0 = (tb % TRN_BX) * 32;
        const int dy0 = (tb / TRN_BX) * 32;
        const int tx  = threadIdx.x & 31;
        const int ty  = threadIdx.x >> 5;          // 0..1
#pragma unroll
        for (int j = 0; j < 32; j += 2) {
            int r = dy0 + ty + j, c = nx0 + tx;
            float v = 0.f;
            if (c < NNODES) v = w_out[(size_t)r * NNODES + c];
            tile[ty + j][tx] = v;
        }
        __syncthreads();
#pragma unroll
        for (int j = 0; j < 32; j += 2) {
            int r = nx0 + ty + j, c = dy0 + tx;
            if (r < NNODES) g_wout_t[(size_t)r * DOUT + c] = tile[tx][ty + j];
        }
        return;
    }

    // -------- traverse partition --------
    const int tok  = blockIdx.x >> 1;
    const int h    = threadIdx.x >> 5;             // half: 0 or 1
    const int lane = threadIdx.x & 31;

    const float4* __restrict__ xr4 =
        reinterpret_cast<const float4*>(x + (size_t)tok * DIN) + h * 256;
    float4 xr[8];
#pragma unroll
    for (int j = 0; j < 8; j++) xr[j] = xr4[j * 32 + lane];

    // w_in rows as float4, offset to this warp's half; row stride = 512 float4
    const float4* __restrict__ wb =
        reinterpret_cast<const float4*>(w_in) + h * 256;

    float4 inA[8], inB[8];

    // ---- level 0: node 0 ----
#pragma unroll
    for (int j = 0; j < 8; j++) inA[j] = wb[j * 32 + lane];          // row 0
    float p = dot8(xr, inA);
    // speculative prefetch children of node 0 (rows 1, 2)
#pragma unroll
    for (int j = 0; j < 8; j++) inA[j] = wb[(size_t)1 * 512 + j * 32 + lane];
#pragma unroll
    for (int j = 0; j < 8; j++) inB[j] = wb[(size_t)2 * 512 + j * 32 + lane];
#pragma unroll
    for (int off = 16; off > 0; off >>= 1)
        p += __shfl_xor_sync(0xffffffffu, p, off);
    if (lane == 0) hx[0][h] = p;
    __syncthreads();
    float s = hx[0][0] + hx[0][1];
    if (h == 0 && lane == 0) {
        g_nodes[tok * NLEV + 0] = 0;
        g_gel[tok * NLEV + 0]   = gelu_exact(s);
    }

    int cur = 0;
#pragma unroll
    for (int l = 1; l < NLEV; l++) {
        const int bit = (s >= 0.0f) ? 1 : 0;
        cur = cur * 2 + 1 + bit;
        // dots with both prefetched children; select by bit
        float pA = dot8(xr, inA);
        float pB = dot8(xr, inB);
        p = bit ? pB : pA;
        // prefetch both children of the new node (needed at level l+1)
        if (l < DEPTH) {
            const float4* __restrict__ rA = wb + (size_t)(2 * cur + 1) * 512;
            const float4* __restrict__ rB = wb + (size_t)(2 * cur + 2) * 512;
#pragma unroll
            for (int j = 0; j < 8; j++) inA[j] = rA[j * 32 + lane];
#pragma unroll
            for (int j = 0; j < 8; j++) inB[j] = rB[j * 32 + lane];
        }
        // reduce + cross-warp combine (loads above land during this)
#pragma unroll
        for (int off = 16; off > 0; off >>= 1)
            p += __shfl_xor_sync(0xffffffffu, p, off);
        if (lane == 0) hx[l & 1][h] = p;
        __syncthreads();
        s = hx[l & 1][0] + hx[l & 1][1];
        if (h == 0 && lane == 0) {
            g_nodes[tok * NLEV + l] = (unsigned short)cur;
            g_gel[tok * NLEV + l]   = gelu_exact(s);
        }
    }
    if (h == 0 && lane == 0)
        atomicAdd(&g_hist[cur - LEAF0], 1);      // cur == level-11 node (leaf)
}

// ---------------------------------------------------------------------------
// Fused scan + scatter, one CTA of 1024 threads.
// ---------------------------------------------------------------------------
__global__ __launch_bounds__(1024) void scan_scatter_kernel() {
    __shared__ int s0[NLEAF];
    __shared__ int s1[NLEAF];
    const int t = threadIdx.x;
    s0[t]        = g_hist[t];
    s0[t + 1024] = g_hist[t + 1024];
    __syncthreads();
    int* src = s0; int* dst = s1;
    for (int off = 1; off < NLEAF; off <<= 1) {
#pragma unroll
        for (int k = 0; k < 2; k++) {
            int i = t + k * 1024;
            int v = src[i];
            if (i >= off) v += src[i - off];
            dst[i] = v;
        }
        __syncthreads();
        int* tmp = src; src = dst; dst = tmp;
    }
#pragma unroll
    for (int k = 0; k < 2; k++) {
        int i = t + k * 1024;
        dst[i] = (i == 0) ? 0 : src[i - 1];
    }
    __syncthreads();
#pragma unroll
    for (int k = 0; k < 8; k++) {
        int tok  = t + k * 1024;
        int leaf = (int)g_nodes[tok * NLEV + DEPTH] - LEAF0;
        int pos  = atomicAdd(&dst[leaf], 1);
        g_perm[pos] = tok;
    }
}

// ---------------------------------------------------------------------------
// Accumulate: 512-thread CTA = 8 leaf-sorted tokens (2 warps/token).
// Same-leaf tokens share all 12 w_out_t rows through L1.
// ---------------------------------------------------------------------------
__global__ __launch_bounds__(512, 2) void accum_kernel(float* __restrict__ out) {
    __shared__ int   s_tok[8];
    __shared__ int   s_node[8][NLEV];
    __shared__ float s_gel[8][NLEV];

    const int pair = threadIdx.x >> 6;    // 0..7: token slot
    const int h    = (threadIdx.x >> 5) & 1;
    const int lane = threadIdx.x & 31;

    if (threadIdx.x < 8) s_tok[threadIdx.x] = g_perm[blockIdx.x * 8 + threadIdx.x];
    __syncthreads();
    if (threadIdx.x < 8 * NLEV) {
        int p = threadIdx.x / NLEV, l = threadIdx.x % NLEV;
        int tk = s_tok[p];
        s_node[p][l] = (int)g_nodes[tk * NLEV + l];
        s_gel[p][l]  = g_gel[tk * NLEV + l];
    }
    __syncthreads();

    float4 acc[8];
#pragma unroll
    for (int j = 0; j < 8; j++) acc[j] = make_float4(0.f, 0.f, 0.f, 0.f);

#pragma unroll
    for (int l = 0; l < NLEV; l++) {
        const int   node = s_node[pair][l];
        const float gl   = s_gel[pair][l];
        const float4* __restrict__ w =
            reinterpret_cast<const float4*>(g_wout_t + (size_t)node * DOUT) + h * 256;
#pragma unroll
        for (int j = 0; j < 8; j++) {
            float4 wv = w[j * 32 + lane];
            acc[j].x += gl * wv.x;
            acc[j].y += gl * wv.y;
            acc[j].z += gl * wv.z;
            acc[j].w += gl * wv.w;
        }
    }

    const int tok = s_tok[pair];
    float4* __restrict__ o =
        reinterpret_cast<float4*>(out + (size_t)tok * DOUT) + h * 256;
#pragma unroll
    for (int j = 0; j < 8; j++) o[j * 32 + lane] = acc[j];
}

// ---------------------------------------------------------------------------
extern "C" void kernel_launch(void* const* d_in, const int* in_sizes, int n_in,
                              void* d_out, int out_size) {
    const float* x     = (const float*)d_in[0];
    const float* w_in  = (const float*)d_in[1];
    const float* w_out = (const float*)d_in[2];
    float* out = (float*)d_out;

    void* hist_ptr;
    cudaGetSymbolAddress(&hist_ptr, g_hist);
    cudaMemsetAsync(hist_ptr, 0, NLEAF * sizeof(int));

    fused_traverse_kernel<<<2 * NTOK, 64>>>(x, w_in, w_out);  // even=traverse, odd=transpose
    scan_scatter_kernel<<<1, 1024>>>();
    accum_kernel<<<NTOK / 8, 512>>>(out);
}

// round 5
// speedup vs baseline: 1.1736x; 1.1736x over previous
#include <cuda_runtime.h>
#include <cuda_bf16.h>
#include <math.h>

#define B_ 4
#define S_ 2048
#define DIN 2048
#define DOUT 2048
#define DEPTH 11
#define NLEV (DEPTH + 1)          // 12
#define NNODES 4095
#define NTOK (B_ * S_)            // 8192
#define NLEAF 2048
#define LEAF0 2047

#define TRN_BX 128                // ceil(4095/32)
#define TRN_BY 64                 // 2048/32
#define TRN_BLOCKS (TRN_BX * TRN_BY)   // 8192 == NTOK -> clean odd/even interleave

// Static scratch
__device__ float          g_wout_t[(size_t)NNODES * DOUT];
__device__ float          g_gel[NTOK * NLEV];
__device__ unsigned short g_leaf[NTOK];       // leaf bucket (0..2047)
__device__ int            g_hist[NLEAF];
__device__ int            g_perm[NTOK];

__device__ __forceinline__ float gelu_exact(float s) {
    return 0.5f * s * (1.0f + erff(s * 0.70710678118654752440f));
}

// ---------------------------------------------------------------------------
// Fused: even blocks = traverse (1 token per 128-thread CTA, 4 warps x 512
// dims, x in 16 regs/lane); odd blocks = transpose w_out.
// ---------------------------------------------------------------------------
__global__ __launch_bounds__(128) void fused_traverse_kernel(
    const float* __restrict__ x,
    const float* __restrict__ w_in,
    const float* __restrict__ w_out)
{
    __shared__ float tile[32][33];     // transpose path
    __shared__ float part[2][4];       // traverse path: [level parity][quarter]

    if (blockIdx.x & 1) {
        // ---- transpose partition: w_out [DOUT,NNODES] -> g_wout_t ----
        const int tb  = blockIdx.x >> 1;
        const int nx0 = (tb % TRN_BX) * 32;
        const int dy0 = (tb / TRN_BX) * 32;
        const int tx  = threadIdx.x & 31;
        const int ty  = threadIdx.x >> 5;          // 0..3
#pragma unroll
        for (int j = 0; j < 32; j += 4) {
            int r = dy0 + ty + j, c = nx0 + tx;
            float v = 0.f;
            if (c < NNODES) v = w_out[(size_t)r * NNODES + c];
            tile[ty + j][tx] = v;
        }
        __syncthreads();
#pragma unroll
        for (int j = 0; j < 32; j += 4) {
            int r = nx0 + ty + j, c = dy0 + tx;
            if (r < NNODES) g_wout_t[(size_t)r * DOUT + c] = tile[tx][ty + j];
        }
        return;
    }

    // ---- traverse partition ----
    const int tok  = blockIdx.x >> 1;
    const int q    = threadIdx.x >> 5;             // quarter 0..3 (512 dims each)
    const int lane = threadIdx.x & 31;

    const float4* __restrict__ xq =
        reinterpret_cast<const float4*>(x + (size_t)tok * DIN) + q * 128;
    float4 xr[4];
#pragma unroll
    for (int j = 0; j < 4; j++) xr[j] = xq[j * 32 + lane];

    const float4* __restrict__ wb =
        reinterpret_cast<const float4*>(w_in) + q * 128;   // + cur*512 per level

    int cur = 0;
#pragma unroll
    for (int l = 0; l < NLEV; l++) {
        const float4* __restrict__ w = wb + (size_t)cur * 512;
        float4 a = w[0 * 32 + lane];
        float4 b = w[1 * 32 + lane];
        float4 c = w[2 * 32 + lane];
        float4 d = w[3 * 32 + lane];
        float p0 = xr[0].x * a.x + xr[0].y * a.y + xr[0].z * a.z + xr[0].w * a.w;
        float p1 = xr[1].x * b.x + xr[1].y * b.y + xr[1].z * b.z + xr[1].w * b.w;
        float p2 = xr[2].x * c.x + xr[2].y * c.y + xr[2].z * c.z + xr[2].w * c.w;
        float p3 = xr[3].x * d.x + xr[3].y * d.y + xr[3].z * d.z + xr[3].w * d.w;
        float p = (p0 + p1) + (p2 + p3);
#pragma unroll
        for (int off = 16; off > 0; off >>= 1)
            p += __shfl_xor_sync(0xffffffffu, p, off);
        if (lane == 0) part[l & 1][q] = p;
        __syncthreads();
        const float s = (part[l & 1][0] + part[l & 1][1])
                      + (part[l & 1][2] + part[l & 1][3]);
        if (threadIdx.x == 0) g_gel[tok * NLEV + l] = gelu_exact(s);
        cur = cur * 2 + 1 + (s >= 0.0f ? 1 : 0);
    }
    if (threadIdx.x == 0) {
        const int leaf = ((cur - 1) >> 1) - LEAF0;   // level-11 node bucket
        g_leaf[tok] = (unsigned short)leaf;
        atomicAdd(&g_hist[leaf], 1);
    }
}

// ---------------------------------------------------------------------------
// Fused scan + scatter, one CTA of 1024 threads.
// ---------------------------------------------------------------------------
__global__ __launch_bounds__(1024) void scan_scatter_kernel() {
    __shared__ int s0[NLEAF];
    __shared__ int s1[NLEAF];
    const int t = threadIdx.x;
    s0[t]        = g_hist[t];
    s0[t + 1024] = g_hist[t + 1024];
    __syncthreads();
    int* src = s0; int* dst = s1;
    for (int off = 1; off < NLEAF; off <<= 1) {
#pragma unroll
        for (int k = 0; k < 2; k++) {
            int i = t + k * 1024;
            int v = src[i];
            if (i >= off) v += src[i - off];
            dst[i] = v;
        }
        __syncthreads();
        int* tmp = src; src = dst; dst = tmp;
    }
#pragma unroll
    for (int k = 0; k < 2; k++) {
        int i = t + k * 1024;
        dst[i] = (i == 0) ? 0 : src[i - 1];
    }
    __syncthreads();
#pragma unroll
    for (int k = 0; k < 8; k++) {
        int tok  = t + k * 1024;
        int leaf = (int)g_leaf[tok];
        int pos  = atomicAdd(&dst[leaf], 1);
        g_perm[pos] = tok;
    }
}

// ---------------------------------------------------------------------------
// Accumulate: 512-thread CTA = 8 leaf-sorted tokens, 2 warps per token.
// Node ids recomputed from the leaf; 12 independent row gathers (high MLP).
// ---------------------------------------------------------------------------
__global__ __launch_bounds__(512, 2) void accum_kernel(float* __restrict__ out) {
    __shared__ int   s_tok[8];
    __shared__ int   s_leafp1[8];          // leaf node id + 1 (for shift trick)
    __shared__ float s_gel[8][NLEV];

    const int slot = threadIdx.x >> 6;     // 0..7
    const int h    = (threadIdx.x >> 5) & 1;
    const int lane = threadIdx.x & 31;

    if (threadIdx.x < 8) {
        int tk = g_perm[blockIdx.x * 8 + threadIdx.x];
        s_tok[threadIdx.x]    = tk;
        s_leafp1[threadIdx.x] = ((int)g_leaf[tk] + LEAF0) + 1;   // node11 + 1
    }
    __syncthreads();
    if (threadIdx.x < 8 * NLEV) {
        int p = threadIdx.x / NLEV, l = threadIdx.x % NLEV;
        s_gel[p][l] = g_gel[s_tok[p] * NLEV + l];
    }
    __syncthreads();

    const int leafp1 = s_leafp1[slot];

    float4 acc[8];
#pragma unroll
    for (int j = 0; j < 8; j++) acc[j] = make_float4(0.f, 0.f, 0.f, 0.f);

#pragma unroll
    for (int l = 0; l < NLEV; l++) {
        const int   node = (leafp1 >> (DEPTH - l)) - 1;
        const float gl   = s_gel[slot][l];
        const float4* __restrict__ w =
            reinterpret_cast<const float4*>(g_wout_t + (size_t)node * DOUT) + h * 256;
#pragma unroll
        for (int j = 0; j < 8; j++) {
            float4 wv = w[j * 32 + lane];
            acc[j].x += gl * wv.x;
            acc[j].y += gl * wv.y;
            acc[j].z += gl * wv.z;
            acc[j].w += gl * wv.w;
        }
    }

    const int tok = s_tok[slot];
    float4* __restrict__ o =
        reinterpret_cast<float4*>(out + (size_t)tok * DOUT) + h * 256;
#pragma unroll
    for (int j = 0; j < 8; j++) o[j * 32 + lane] = acc[j];
}

// ---------------------------------------------------------------------------
extern "C" void kernel_launch(void* const* d_in, const int* in_sizes, int n_in,
                              void* d_out, int out_size) {
    const float* x     = (const float*)d_in[0];
    const float* w_in  = (const float*)d_in[1];
    const float* w_out = (const float*)d_in[2];
    float* out = (float*)d_out;

    void* hist_ptr;
    cudaGetSymbolAddress(&hist_ptr, g_hist);
    cudaMemsetAsync(hist_ptr, 0, NLEAF * sizeof(int));

    fused_traverse_kernel<<<2 * NTOK, 128>>>(x, w_in, w_out);  // even=traverse, odd=transpose
    scan_scatter_kernel<<<1, 1024>>>();
    accum_kernel<<<NTOK / 8, 512>>>(out);
}

// round 6
// speedup vs baseline: 1.2972x; 1.1053x over previous
#include <cuda_runtime.h>
#include <cuda_bf16.h>
#include <math.h>

#define B_ 4
#define S_ 2048
#define DIN 2048
#define DOUT 2048
#define DEPTH 11
#define NLEV (DEPTH + 1)          // 12
#define NNODES 4095
#define NTOK (B_ * S_)            // 8192
#define NLEAF 2048
#define LEAF0 2047

#define TRN_BX 128                // ceil(4095/32)
#define TRN_BY 64                 // 2048/32

// accum config
#define TPC 8                     // tokens per CTA
#define HSZ 128                   // node hash table size (max union = 96)

// Static scratch
__device__ float          g_wout_t[(size_t)NNODES * DOUT];
__device__ float          g_gel[NTOK * NLEV];
__device__ unsigned short g_leaf[NTOK];       // leaf bucket (0..2047)
__device__ int            g_hist[NLEAF];
__device__ int            g_perm[NTOK];

__device__ __forceinline__ float gelu_exact(float s) {
    return 0.5f * s * (1.0f + erff(s * 0.70710678118654752440f));
}

// ---------------------------------------------------------------------------
// Fused: even blocks = traverse (1 token per 128-thread CTA, 4 warps x 512
// dims); odd blocks = transpose w_out.   (unchanged R5 winner)
// ---------------------------------------------------------------------------
__global__ __launch_bounds__(128) void fused_traverse_kernel(
    const float* __restrict__ x,
    const float* __restrict__ w_in,
    const float* __restrict__ w_out)
{
    __shared__ float tile[32][33];
    __shared__ float part[2][4];

    if (blockIdx.x & 1) {
        const int tb  = blockIdx.x >> 1;
        const int nx0 = (tb % TRN_BX) * 32;
        const int dy0 = (tb / TRN_BX) * 32;
        const int tx  = threadIdx.x & 31;
        const int ty  = threadIdx.x >> 5;
#pragma unroll
        for (int j = 0; j < 32; j += 4) {
            int r = dy0 + ty + j, c = nx0 + tx;
            float v = 0.f;
            if (c < NNODES) v = w_out[(size_t)r * NNODES + c];
            tile[ty + j][tx] = v;
        }
        __syncthreads();
#pragma unroll
        for (int j = 0; j < 32; j += 4) {
            int r = nx0 + ty + j, c = dy0 + tx;
            if (r < NNODES) g_wout_t[(size_t)r * DOUT + c] = tile[tx][ty + j];
        }
        return;
    }

    const int tok  = blockIdx.x >> 1;
    const int q    = threadIdx.x >> 5;
    const int lane = threadIdx.x & 31;

    const float4* __restrict__ xq =
        reinterpret_cast<const float4*>(x + (size_t)tok * DIN) + q * 128;
    float4 xr[4];
#pragma unroll
    for (int j = 0; j < 4; j++) xr[j] = xq[j * 32 + lane];

    const float4* __restrict__ wb =
        reinterpret_cast<const float4*>(w_in) + q * 128;

    int cur = 0;
#pragma unroll
    for (int l = 0; l < NLEV; l++) {
        const float4* __restrict__ w = wb + (size_t)cur * 512;
        float4 a = w[0 * 32 + lane];
        float4 b = w[1 * 32 + lane];
        float4 c = w[2 * 32 + lane];
        float4 d = w[3 * 32 + lane];
        float p0 = xr[0].x * a.x + xr[0].y * a.y + xr[0].z * a.z + xr[0].w * a.w;
        float p1 = xr[1].x * b.x + xr[1].y * b.y + xr[1].z * b.z + xr[1].w * b.w;
        float p2 = xr[2].x * c.x + xr[2].y * c.y + xr[2].z * c.z + xr[2].w * c.w;
        float p3 = xr[3].x * d.x + xr[3].y * d.y + xr[3].z * d.z + xr[3].w * d.w;
        float p = (p0 + p1) + (p2 + p3);
#pragma unroll
        for (int off = 16; off > 0; off >>= 1)
            p += __shfl_xor_sync(0xffffffffu, p, off);
        if (lane == 0) part[l & 1][q] = p;
        __syncthreads();
        const float s = (part[l & 1][0] + part[l & 1][1])
                      + (part[l & 1][2] + part[l & 1][3]);
        if (threadIdx.x == 0) g_gel[tok * NLEV + l] = gelu_exact(s);
        cur = cur * 2 + 1 + (s >= 0.0f ? 1 : 0);
    }
    if (threadIdx.x == 0) {
        const int leaf = ((cur - 1) >> 1) - LEAF0;
        g_leaf[tok] = (unsigned short)leaf;
        atomicAdd(&g_hist[leaf], 1);
    }
}

// ---------------------------------------------------------------------------
// Fused scan + scatter, one CTA of 1024 threads.
// ---------------------------------------------------------------------------
__global__ __launch_bounds__(1024) void scan_scatter_kernel() {
    __shared__ int s0[NLEAF];
    __shared__ int s1[NLEAF];
    const int t = threadIdx.x;
    s0[t]        = g_hist[t];
    s0[t + 1024] = g_hist[t + 1024];
    __syncthreads();
    int* src = s0; int* dst = s1;
    for (int off = 1; off < NLEAF; off <<= 1) {
#pragma unroll
        for (int k = 0; k < 2; k++) {
            int i = t + k * 1024;
            int v = src[i];
            if (i >= off) v += src[i - off];
            dst[i] = v;
        }
        __syncthreads();
        int* tmp = src; src = dst; dst = tmp;
    }
#pragma unroll
    for (int k = 0; k < 2; k++) {
        int i = t + k * 1024;
        dst[i] = (i == 0) ? 0 : src[i - 1];
    }
    __syncthreads();
#pragma unroll
    for (int k = 0; k < 8; k++) {
        int tok  = t + k * 1024;
        int leaf = (int)g_leaf[tok];
        int pos  = atomicAdd(&dst[leaf], 1);
        g_perm[pos] = tok;
    }
}

// ---------------------------------------------------------------------------
// Accumulate: 256-thread CTA = 8 leaf-sorted tokens.
// Build the union of the 8 tokens' path nodes in a smem hash, load each
// distinct w_out_t row ONCE, and FFMA into all 8 token accumulators.
// ---------------------------------------------------------------------------
__global__ __launch_bounds__(256, 2) void accum_kernel(float* __restrict__ out) {
    __shared__ int   s_key[HSZ];              // node id or -1
    __shared__ float s_gl[HSZ][TPC];          // coefficient per (node, token)
    __shared__ int   s_list[HSZ];             // compacted occupied slots
    __shared__ int   s_cnt;
    __shared__ int   s_tok[TPC];
    __shared__ int   s_leafp1[TPC];

    const int tid = threadIdx.x;

    // init hash
#pragma unroll
    for (int k = tid; k < HSZ; k += 256) s_key[k] = -1;
#pragma unroll
    for (int k = tid; k < HSZ * TPC; k += 256)
        (&s_gl[0][0])[k] = 0.0f;
    if (tid == 0) s_cnt = 0;
    if (tid < TPC) {
        int tk = g_perm[blockIdx.x * TPC + tid];
        s_tok[tid]    = tk;
        s_leafp1[tid] = ((int)g_leaf[tk] + LEAF0) + 1;   // node11 + 1
    }
    __syncthreads();

    // insert 96 (node, token, gl) entries
    if (tid < TPC * NLEV) {
        const int t = tid / NLEV;
        const int l = tid % NLEV;
        const int node = (s_leafp1[t] >> (DEPTH - l)) - 1;
        const float gl = g_gel[s_tok[t] * NLEV + l];
        unsigned slot = ((unsigned)node * 2654435761u >> 16) & (HSZ - 1);
        while (true) {
            int prev = atomicCAS(&s_key[slot], -1, node);
            if (prev == -1 || prev == node) break;
            slot = (slot + 1) & (HSZ - 1);
        }
        s_gl[slot][t] = gl;                    // unique (node, t) -> no race
    }
    __syncthreads();

    // compact occupied slots
    for (int k = tid; k < HSZ; k += 256) {
        if (s_key[k] != -1) {
            int pos = atomicAdd(&s_cnt, 1);
            s_list[pos] = k;
        }
    }
    __syncthreads();
    const int cnt = s_cnt;

    // accumulators: 8 tokens x 2 float4 per thread (thread owns float4 idx tid, tid+256)
    float4 acc0[TPC], acc1[TPC];
#pragma unroll
    for (int t = 0; t < TPC; t++) {
        acc0[t] = make_float4(0.f, 0.f, 0.f, 0.f);
        acc1[t] = make_float4(0.f, 0.f, 0.f, 0.f);
    }

    for (int i = 0; i < cnt; i++) {
        const int slot = s_list[i];
        const int node = s_key[slot];
        const float4* __restrict__ w =
            reinterpret_cast<const float4*>(g_wout_t + (size_t)node * DOUT);
        const float4 r0 = w[tid];
        const float4 r1 = w[tid + 256];
        float gl[TPC];
#pragma unroll
        for (int t = 0; t < TPC; t++) gl[t] = s_gl[slot][t];
#pragma unroll
        for (int t = 0; t < TPC; t++) {
            acc0[t].x += gl[t] * r0.x;  acc0[t].y += gl[t] * r0.y;
            acc0[t].z += gl[t] * r0.z;  acc0[t].w += gl[t] * r0.w;
            acc1[t].x += gl[t] * r1.x;  acc1[t].y += gl[t] * r1.y;
            acc1[t].z += gl[t] * r1.z;  acc1[t].w += gl[t] * r1.w;
        }
    }

    // write out
#pragma unroll
    for (int t = 0; t < TPC; t++) {
        float4* __restrict__ o =
            reinterpret_cast<float4*>(out + (size_t)s_tok[t] * DOUT);
        o[tid]       = acc0[t];
        o[tid + 256] = acc1[t];
    }
}

// ---------------------------------------------------------------------------
extern "C" void kernel_launch(void* const* d_in, const int* in_sizes, int n_in,
                              void* d_out, int out_size) {
    const float* x     = (const float*)d_in[0];
    const float* w_in  = (const float*)d_in[1];
    const float* w_out = (const float*)d_in[2];
    float* out = (float*)d_out;

    void* hist_ptr;
    cudaGetSymbolAddress(&hist_ptr, g_hist);
    cudaMemsetAsync(hist_ptr, 0, NLEAF * sizeof(int));

    fused_traverse_kernel<<<2 * NTOK, 128>>>(x, w_in, w_out);
    scan_scatter_kernel<<<1, 1024>>>();
    accum_kernel<<<NTOK / TPC, 256>>>(out);
}

// round 7
// speedup vs baseline: 1.3225x; 1.0194x over previous
#include <cuda_runtime.h>
#include <cuda_bf16.h>
#include <math.h>

#define B_ 4
#define S_ 2048
#define DIN 2048
#define DOUT 2048
#define DEPTH 11
#define NLEV (DEPTH + 1)          // 12
#define NNODES 4095
#define NTOK (B_ * S_)            // 8192
#define NLEAF 2048
#define LEAF0 2047

#define TRN_BX 128                // ceil(4095/32)

// accum config
#define TPC 8                     // tokens per CTA
#define HSZ 128                   // node hash table size

// Static scratch
__device__ float          g_wout_t[(size_t)NNODES * DOUT];
__device__ float          g_gel[NTOK * NLEV];
__device__ unsigned short g_leaf[NTOK];
__device__ int            g_hist[NLEAF];     // zero-init; re-zeroed by scan_scatter
__device__ int            g_perm[NTOK];

__device__ __forceinline__ float gelu_exact(float s) {
    return 0.5f * s * (1.0f + erff(s * 0.70710678118654752440f));
}

// ---------------------------------------------------------------------------
// Fused: blockIdx.x % 3 == 0 -> traverse 2 tokens; else transpose tile.
// 4096 traverse CTAs (2 tokens each) + 8192 transpose CTAs, interleaved.
// ---------------------------------------------------------------------------
__global__ __launch_bounds__(128) void fused_traverse_kernel(
    const float* __restrict__ x,
    const float* __restrict__ w_in,
    const float* __restrict__ w_out)
{
    __shared__ float tile[32][33];
    __shared__ float part[2][2][4];      // [parity][token][quarter]

    const int m = blockIdx.x % 3;
    const int g = blockIdx.x / 3;

    if (m != 0) {
        // ---- transpose partition: tile id in [0, 8192) ----
        const int tb  = g * 2 + (m - 1);
        const int nx0 = (tb % TRN_BX) * 32;
        const int dy0 = (tb / TRN_BX) * 32;
        const int tx  = threadIdx.x & 31;
        const int ty  = threadIdx.x >> 5;
#pragma unroll
        for (int j = 0; j < 32; j += 4) {
            int r = dy0 + ty + j, c = nx0 + tx;
            float v = 0.f;
            if (c < NNODES) v = w_out[(size_t)r * NNODES + c];
            tile[ty + j][tx] = v;
        }
        __syncthreads();
#pragma unroll
        for (int j = 0; j < 32; j += 4) {
            int r = nx0 + ty + j, c = dy0 + tx;
            if (r < NNODES) g_wout_t[(size_t)r * DOUT + c] = tile[tx][ty + j];
        }
        return;
    }

    // ---- traverse partition: 2 independent tokens per CTA ----
    const int tokA = g * 2;
    const int tokB = g * 2 + 1;
    const int q    = threadIdx.x >> 5;            // quarter (512 dims)
    const int lane = threadIdx.x & 31;

    const float4* __restrict__ xqA =
        reinterpret_cast<const float4*>(x + (size_t)tokA * DIN) + q * 128;
    const float4* __restrict__ xqB =
        reinterpret_cast<const float4*>(x + (size_t)tokB * DIN) + q * 128;
    float4 xA[4], xB[4];
#pragma unroll
    for (int j = 0; j < 4; j++) xA[j] = xqA[j * 32 + lane];
#pragma unroll
    for (int j = 0; j < 4; j++) xB[j] = xqB[j * 32 + lane];

    const float4* __restrict__ wb =
        reinterpret_cast<const float4*>(w_in) + q * 128;

    int curA = 0, curB = 0;
#pragma unroll
    for (int l = 0; l < NLEV; l++) {
        const float4* __restrict__ wA = wb + (size_t)curA * 512;
        const float4* __restrict__ wB = wb + (size_t)curB * 512;
        // 8 independent loads (2 tokens x 4)
        float4 a0 = wA[0 * 32 + lane];
        float4 a1 = wA[1 * 32 + lane];
        float4 a2 = wA[2 * 32 + lane];
        float4 a3 = wA[3 * 32 + lane];
        float4 b0 = wB[0 * 32 + lane];
        float4 b1 = wB[1 * 32 + lane];
        float4 b2 = wB[2 * 32 + lane];
        float4 b3 = wB[3 * 32 + lane];

        float pA = (xA[0].x * a0.x + xA[0].y * a0.y + xA[0].z * a0.z + xA[0].w * a0.w)
                 + (xA[1].x * a1.x + xA[1].y * a1.y + xA[1].z * a1.z + xA[1].w * a1.w)
                 + (xA[2].x * a2.x + xA[2].y * a2.y + xA[2].z * a2.z + xA[2].w * a2.w)
                 + (xA[3].x * a3.x + xA[3].y * a3.y + xA[3].z * a3.z + xA[3].w * a3.w);
        float pB = (xB[0].x * b0.x + xB[0].y * b0.y + xB[0].z * b0.z + xB[0].w * b0.w)
                 + (xB[1].x * b1.x + xB[1].y * b1.y + xB[1].z * b1.z + xB[1].w * b1.w)
                 + (xB[2].x * b2.x + xB[2].y * b2.y + xB[2].z * b2.z + xB[2].w * b2.w)
                 + (xB[3].x * b3.x + xB[3].y * b3.y + xB[3].z * b3.z + xB[3].w * b3.w);

        // two independent butterfly reduces, interleaved
#pragma unroll
        for (int off = 16; off > 0; off >>= 1) {
            pA += __shfl_xor_sync(0xffffffffu, pA, off);
            pB += __shfl_xor_sync(0xffffffffu, pB, off);
        }
        if (lane == 0) {
            part[l & 1][0][q] = pA;
            part[l & 1][1][q] = pB;
        }
        __syncthreads();
        const float sA = (part[l & 1][0][0] + part[l & 1][0][1])
                       + (part[l & 1][0][2] + part[l & 1][0][3]);
        const float sB = (part[l & 1][1][0] + part[l & 1][1][1])
                       + (part[l & 1][1][2] + part[l & 1][1][3]);
        if (threadIdx.x == 0)  g_gel[tokA * NLEV + l] = gelu_exact(sA);
        if (threadIdx.x == 32) g_gel[tokB * NLEV + l] = gelu_exact(sB);
        curA = curA * 2 + 1 + (sA >= 0.0f ? 1 : 0);
        curB = curB * 2 + 1 + (sB >= 0.0f ? 1 : 0);
    }
    if (threadIdx.x == 0) {
        const int leaf = ((curA - 1) >> 1) - LEAF0;
        g_leaf[tokA] = (unsigned short)leaf;
        atomicAdd(&g_hist[leaf], 1);
    }
    if (threadIdx.x == 32) {
        const int leaf = ((curB - 1) >> 1) - LEAF0;
        g_leaf[tokB] = (unsigned short)leaf;
        atomicAdd(&g_hist[leaf], 1);
    }
}

// ---------------------------------------------------------------------------
// Fused scan + scatter, one CTA of 1024 threads. Also re-zeroes g_hist for
// the next graph replay (statics start zeroed for the first call).
// ---------------------------------------------------------------------------
__global__ __launch_bounds__(1024) void scan_scatter_kernel() {
    __shared__ int s0[NLEAF];
    __shared__ int s1[NLEAF];
    const int t = threadIdx.x;
    s0[t]        = g_hist[t];
    s0[t + 1024] = g_hist[t + 1024];
    g_hist[t]        = 0;
    g_hist[t + 1024] = 0;
    __syncthreads();
    int* src = s0; int* dst = s1;
    for (int off = 1; off < NLEAF; off <<= 1) {
#pragma unroll
        for (int k = 0; k < 2; k++) {
            int i = t + k * 1024;
            int v = src[i];
            if (i >= off) v += src[i - off];
            dst[i] = v;
        }
        __syncthreads();
        int* tmp = src; src = dst; dst = tmp;
    }
#pragma unroll
    for (int k = 0; k < 2; k++) {
        int i = t + k * 1024;
        dst[i] = (i == 0) ? 0 : src[i - 1];
    }
    __syncthreads();
#pragma unroll
    for (int k = 0; k < 8; k++) {
        int tok  = t + k * 1024;
        int leaf = (int)g_leaf[tok];
        int pos  = atomicAdd(&dst[leaf], 1);
        g_perm[pos] = tok;
    }
}

// ---------------------------------------------------------------------------
// Accumulate: 512-thread CTA = 8 leaf-sorted tokens; thread owns ONE float4
// of the 2048-dim row; acc = 8 x float4 = 32 regs -> 2 CTAs/SM (32 warps).
// Each distinct node row loaded once, FFMA'd into all 8 token accumulators.
// ---------------------------------------------------------------------------
__global__ __launch_bounds__(512, 2) void accum_kernel(float* __restrict__ out) {
    __shared__ int   s_key[HSZ];
    __shared__ float s_gl[HSZ][TPC];
    __shared__ int   s_list[HSZ];
    __shared__ int   s_cnt;
    __shared__ int   s_tok[TPC];
    __shared__ int   s_leafp1[TPC];

    const int tid = threadIdx.x;

#pragma unroll
    for (int k = tid; k < HSZ; k += 512) s_key[k] = -1;
#pragma unroll
    for (int k = tid; k < HSZ * TPC; k += 512) (&s_gl[0][0])[k] = 0.0f;
    if (tid == 0) s_cnt = 0;
    if (tid < TPC) {
        int tk = g_perm[blockIdx.x * TPC + tid];
        s_tok[tid]    = tk;
        s_leafp1[tid] = ((int)g_leaf[tk] + LEAF0) + 1;
    }
    __syncthreads();

    if (tid < TPC * NLEV) {
        const int t = tid / NLEV;
        const int l = tid % NLEV;
        const int node = (s_leafp1[t] >> (DEPTH - l)) - 1;
        const float gl = g_gel[s_tok[t] * NLEV + l];
        unsigned slot = ((unsigned)node * 2654435761u >> 16) & (HSZ - 1);
        while (true) {
            int prev = atomicCAS(&s_key[slot], -1, node);
            if (prev == -1 || prev == node) break;
            slot = (slot + 1) & (HSZ - 1);
        }
        s_gl[slot][t] = gl;
    }
    __syncthreads();

    for (int k = tid; k < HSZ; k += 512) {
        if (s_key[k] != -1) {
            int pos = atomicAdd(&s_cnt, 1);
            s_list[pos] = k;
        }
    }
    __syncthreads();
    const int cnt = s_cnt;

    float4 acc[TPC];
#pragma unroll
    for (int t = 0; t < TPC; t++) acc[t] = make_float4(0.f, 0.f, 0.f, 0.f);

    for (int i = 0; i < cnt; i++) {
        const int slot = s_list[i];
        const int node = s_key[slot];
        const float4 r =
            reinterpret_cast<const float4*>(g_wout_t + (size_t)node * DOUT)[tid];
        float gl[TPC];
#pragma unroll
        for (int t = 0; t < TPC; t++) gl[t] = s_gl[slot][t];
#pragma unroll
        for (int t = 0; t < TPC; t++) {
            acc[t].x += gl[t] * r.x;
            acc[t].y += gl[t] * r.y;
            acc[t].z += gl[t] * r.z;
            acc[t].w += gl[t] * r.w;
        }
    }

#pragma unroll
    for (int t = 0; t < TPC; t++)
        reinterpret_cast<float4*>(out + (size_t)s_tok[t] * DOUT)[tid] = acc[t];
}

// ---------------------------------------------------------------------------
extern "C" void kernel_launch(void* const* d_in, const int* in_sizes, int n_in,
                              void* d_out, int out_size) {
    const float* x     = (const float*)d_in[0];
    const float* w_in  = (const float*)d_in[1];
    const float* w_out = (const float*)d_in[2];
    float* out = (float*)d_out;

    fused_traverse_kernel<<<3 * (NTOK / 2), 128>>>(x, w_in, w_out);
    scan_scatter_kernel<<<1, 1024>>>();
    accum_kernel<<<NTOK / TPC, 512>>>(out);
}